// round 3
// baseline (speedup 1.0000x reference)
#include <cuda_runtime.h>
#include <cuda_bf16.h>
#include <cfloat>
#include <cub/cub.cuh>

#define KC 16
#define DC 64
#define NMAX 131072
#define CHUNK 256
#define NCHUNK_MAX (NMAX / CHUNK)

// ---------------- static device scratch ----------------
__device__ int   g_pred[NMAX];
__device__ int   g_ccx[NCHUNK_MAX * KC];
__device__ int   g_cct[NCHUNK_MAX * KC];
__device__ int   g_cbx[NCHUNK_MAX * KC];
__device__ int   g_cbt[NCHUNK_MAX * KC];
__device__ int   g_cntx[KC], g_cntt[KC], g_m[KC], g_off[KC], g_pow[KC];
__device__ float g_fill[KC];
__device__ float g_loss;
__device__ float g_bufx[2u * NMAX * DC];
__device__ float g_buft[2u * NMAX * DC];

// sortable-uint encode with LSB reserved for source tag (<=1ulp perturbation)
__device__ __forceinline__ unsigned encKey(float f) {
    unsigned u = __float_as_uint(f);
    unsigned s = (u & 0x80000000u) ? ~u : (u | 0x80000000u);
    return s & ~1u;
}
__device__ __forceinline__ float decKey(unsigned key) {
    unsigned s = key & ~1u;
    unsigned u = (s & 0x80000000u) ? (s & 0x7fffffffu) : ~s;
    return __uint_as_float(u);
}

// ---------------- init ----------------
__global__ void initK() {
    int t = threadIdx.x;
    if (t < KC) g_fill[t] = 0.f;
    if (t == 0) g_loss = 0.f;
}

// ---------------- assignment + softmax filling + per-chunk counts ----------------
__global__ void assignK(const float* __restrict__ x, const float* __restrict__ C, int N) {
    __shared__ float4 sC[KC * DC / 4];
    __shared__ float  sCC[KC];
    __shared__ float  sFill[KC];
    __shared__ int    sCnt[KC];
    int tid = threadIdx.x;
    sC[tid] = ((const float4*)C)[tid];
    if (tid < KC) { sFill[tid] = 0.f; sCnt[tid] = 0; }
    __syncthreads();
    if (tid < KC) {
        float cc = 0.f;
        #pragma unroll
        for (int q = 0; q < DC / 4; q++) {
            float4 c = sC[tid * (DC / 4) + q];
            cc += c.x * c.x + c.y * c.y + c.z * c.z + c.w * c.w;
        }
        sCC[tid] = cc;
    }
    __syncthreads();

    int i = blockIdx.x * blockDim.x + tid;
    bool act = i < N;
    float sc[KC];
    int bk = 0;
    if (act) {
        float acc[KC];
        #pragma unroll
        for (int k = 0; k < KC; k++) acc[k] = 0.f;
        const float4* xr = (const float4*)(x + (size_t)i * DC);
        #pragma unroll
        for (int q = 0; q < DC / 4; q++) {
            float4 v = xr[q];
            #pragma unroll
            for (int k = 0; k < KC; k++) {
                float4 c = sC[k * (DC / 4) + q];
                acc[k] += v.x * c.x + v.y * c.y + v.z * c.z + v.w * c.w;
            }
        }
        float best = FLT_MAX;
        #pragma unroll
        for (int k = 0; k < KC; k++) {
            sc[k] = sCC[k] - 2.f * acc[k];
            if (sc[k] < best) { best = sc[k]; bk = k; }
        }
        g_pred[i] = bk;
        float sum = 0.f;
        #pragma unroll
        for (int k = 0; k < KC; k++) { float e = __expf(-4.f * (sc[k] - best)); sc[k] = e; sum += e; }
        float inv = 1.f / sum;
        #pragma unroll
        for (int k = 0; k < KC; k++) sc[k] *= inv;
        atomicAdd(&sCnt[bk], 1);
    } else {
        #pragma unroll
        for (int k = 0; k < KC; k++) sc[k] = 0.f;
    }
    int lane = tid & 31;
    #pragma unroll
    for (int k = 0; k < KC; k++) {
        float v = sc[k];
        v += __shfl_down_sync(0xffffffffu, v, 16);
        v += __shfl_down_sync(0xffffffffu, v, 8);
        v += __shfl_down_sync(0xffffffffu, v, 4);
        v += __shfl_down_sync(0xffffffffu, v, 2);
        v += __shfl_down_sync(0xffffffffu, v, 1);
        if (lane == 0) atomicAdd(&sFill[k], v);
    }
    __syncthreads();
    if (tid < KC) {
        g_ccx[blockIdx.x * KC + tid] = sCnt[tid];
        atomicAdd(&g_fill[tid], sFill[tid]);
    }
}

// ---------------- per-chunk counts for target ----------------
__global__ void countTK(const int* __restrict__ pr, int N) {
    __shared__ int sCnt[KC];
    int tid = threadIdx.x;
    if (tid < KC) sCnt[tid] = 0;
    __syncthreads();
    int i = blockIdx.x * blockDim.x + tid;
    if (i < N) atomicAdd(&sCnt[pr[i]], 1);
    __syncthreads();
    if (tid < KC) g_cct[blockIdx.x * KC + tid] = sCnt[tid];
}

// ---------------- parallel scan: warp per (src,k) ----------------
__global__ void scanK(int nchunk) {
    int w = threadIdx.x >> 5, lane = threadIdx.x & 31;
    int k = w & 15;
    const int* cc = (w < 16) ? g_ccx : g_cct;
    int* cb       = (w < 16) ? g_cbx : g_cbt;
    int run = 0;
    for (int c0 = 0; c0 < nchunk; c0 += 32) {
        int c = c0 + lane;
        int v = (c < nchunk) ? cc[c * KC + k] : 0;
        int s = v;
        #pragma unroll
        for (int o = 1; o < 32; o <<= 1) {
            int y = __shfl_up_sync(0xffffffffu, s, o);
            if (lane >= o) s += y;
        }
        if (c < nchunk) cb[c * KC + k] = run + s - v;
        run += __shfl_sync(0xffffffffu, s, 31);
    }
    if (lane == 31) { if (w < 16) g_cntx[k] = run; else g_cntt[k] = run; }
    __syncthreads();
    if (threadIdx.x == 0) {
        int off = 0;
        for (int kk = 0; kk < KC; kk++) {
            int m = min(g_cntx[kk], g_cntt[kk]);
            g_m[kk] = m;
            int p = 1;
            while (p < m) p <<= 1;
            if (m == 0) p = 0;
            g_pow[kk] = p;
            g_off[kk] = off;
            off += p;
        }
    }
}

// ---------------- pad fill (only for giant-segment fallback) ----------------
__global__ void fillK() {
    int mx = 0;
    #pragma unroll
    for (int k = 0; k < KC; k++) mx = max(mx, g_m[k]);
    if (mx <= 16384) return;
    size_t n = (size_t)2 * NMAX * DC / 4;
    float4 v = make_float4(FLT_MAX, FLT_MAX, FLT_MAX, FLT_MAX);
    for (size_t i = (size_t)blockIdx.x * blockDim.x + threadIdx.x; i < n;
         i += (size_t)gridDim.x * blockDim.x) {
        ((float4*)g_bufx)[i] = v;
        ((float4*)g_buft)[i] = v;
    }
}

// ---------------- stable scatter into per-(cluster,dim) segments ----------------
__global__ void scatterK(const float* __restrict__ src, const int* __restrict__ predIn,
                         int isx, int N) {
    __shared__ int wcnt[8][KC];
    int tid = threadIdx.x;
    if (tid < 8 * KC) ((int*)wcnt)[tid] = 0;
    __syncthreads();
    const int* pred = isx ? g_pred : predIn;
    int i = blockIdx.x * blockDim.x + tid;
    int lane = tid & 31, w = tid >> 5;
    int k = 0, lr = 0;
    bool act = i < N;
    unsigned ball = __ballot_sync(0xffffffffu, act);
    if (act) {
        k = pred[i];
        unsigned mm = __match_any_sync(ball, k);
        lr = __popc(mm & ((1u << lane) - 1u));
        if (lane == (int)(__ffs(mm) - 1)) wcnt[w][k] = __popc(mm);
    }
    __syncthreads();
    if (act) {
        int base = isx ? g_cbx[blockIdx.x * KC + k] : g_cbt[blockIdx.x * KC + k];
        #pragma unroll
        for (int ww = 0; ww < 8; ww++)
            if (ww < w) base += wcnt[ww][k];
        int r = base + lr;
        int m = g_m[k];
        if (r < m) {
            int P = g_pow[k];
            float* buf = (isx ? g_bufx : g_buft) + (size_t)g_off[k] * DC + r;
            const float4* s4 = (const float4*)(src + (size_t)i * DC);
            #pragma unroll
            for (int q = 0; q < DC / 4; q++) {
                float4 v = s4[q];
                buf[(size_t)(4 * q + 0) * P] = v.x;
                buf[(size_t)(4 * q + 1) * P] = v.y;
                buf[(size_t)(4 * q + 2) * P] = v.z;
                buf[(size_t)(4 * q + 3) * P] = v.w;
            }
        }
    }
}

// ---------------- fused merged sort + W1 integral per (cluster,dim) ----------------
template <int BT>
struct PostTS {
    typename cub::BlockScan<int, BT>::TempStorage scan;
    typename cub::BlockReduce<float, BT>::TempStorage red;
    unsigned bound[BT];
};

template <int BT, int IPT, int LO>
__global__ void __launch_bounds__(BT) wassK() {
    constexpr int CAP = BT * IPT;
    int seg = blockIdx.x;
    int k = seg >> 6, d = seg & 63;
    int m = g_m[k];
    int twoM = 2 * m;
    if (m <= 0 || twoM <= LO || twoM > CAP) return;
    int P = g_pow[k];
    const float* bx = g_bufx + (size_t)g_off[k] * DC + (size_t)d * P;
    const float* bt = g_buft + (size_t)g_off[k] * DC + (size_t)d * P;

    typedef cub::BlockRadixSort<unsigned, BT, IPT> BRS;
    typedef cub::BlockScan<int, BT> BSc;
    typedef cub::BlockReduce<float, BT> BRd;
    extern __shared__ __align__(16) unsigned char smraw[];
    typename BRS::TempStorage* sortTS = reinterpret_cast<typename BRS::TempStorage*>(smraw);
    PostTS<BT>* post = reinterpret_cast<PostTS<BT>*>(smraw);

    unsigned keys[IPT];
    int base = threadIdx.x * IPT;
    #pragma unroll
    for (int j = 0; j < IPT; j++) {
        int idx = base + j;
        if (idx < m)            keys[j] = encKey(bx[idx]) | 1u;       // x: tag 1 -> +1
        else if (idx < twoM)    keys[j] = encKey(bt[idx - m]);        // t: tag 0 -> -1
        else                    keys[j] = 0xFFFFFFFFu;                // pad
    }
    BRS(*sortTS).Sort(keys);
    __syncthreads();

    int loc = 0;
    #pragma unroll
    for (int j = 0; j < IPT; j++) {
        int idx = base + j;
        if (idx < twoM) loc += (keys[j] & 1u) ? 1 : -1;
    }
    int off;
    BSc(post->scan).ExclusiveSum(loc, off);
    __syncthreads();
    post->bound[threadIdx.x] = keys[0];
    __syncthreads();
    unsigned nbound = (threadIdx.x + 1 < BT) ? post->bound[threadIdx.x + 1] : 0xFFFFFFFFu;

    float acc = 0.f;
    int run = off;
    #pragma unroll
    for (int j = 0; j < IPT; j++) {
        int idx = base + j;
        if (idx < twoM) run += (keys[j] & 1u) ? 1 : -1;
        if (idx + 1 < twoM) {
            unsigned nk = (j < IPT - 1) ? keys[j + 1] : nbound;
            acc += (decKey(nk) - decKey(keys[j])) * fabsf((float)run);
        }
    }
    __syncthreads();
    float tot = BRd(post->red).Sum(acc);
    if (threadIdx.x == 0) atomicAdd(&g_loss, tot / ((float)m * (float)DC));
}

// ---------------- fallback: global bitonic for huge segments (m > 16384) ----------------
__global__ void fallbackK() {
    int seg = blockIdx.x;
    int k = seg >> 6, d = seg & 63;
    int m = g_m[k];
    if (m <= 16384) return;
    int P = g_pow[k];
    float* p = (blockIdx.y ? g_buft : g_bufx) + (size_t)g_off[k] * DC + (size_t)d * P;
    for (int size = 2; size <= P; size <<= 1) {
        for (int stride = size >> 1; stride; stride >>= 1) {
            for (int t = threadIdx.x; t < (P >> 1); t += blockDim.x) {
                int low = t & (stride - 1);
                int i = ((t - low) << 1) + low;
                int j = i + stride;
                float a = p[i], b = p[j];
                bool up = ((i & size) == 0);
                if ((a > b) == up) { p[i] = b; p[j] = a; }
            }
            __syncthreads();
        }
    }
}

// ---------------- diff for fallback path only ----------------
__global__ void diffK() {
    int seg = blockIdx.x;
    int k = seg >> 6, d = seg & 63;
    int m = g_m[k];
    if (m <= 16384) return;
    int P = g_pow[k];
    size_t base = (size_t)g_off[k] * DC + (size_t)d * P;
    float s = 0.f;
    for (int i = threadIdx.x; i < m; i += blockDim.x)
        s += fabsf(g_bufx[base + i] - g_buft[base + i]);
    __shared__ float red[256];
    red[threadIdx.x] = s;
    __syncthreads();
    for (int o = 128; o; o >>= 1) {
        if (threadIdx.x < o) red[threadIdx.x] += red[threadIdx.x + o];
        __syncthreads();
    }
    if (threadIdx.x == 0) atomicAdd(&g_loss, red[0] / ((float)m * (float)DC));
}

// ---------------- finalize ----------------
__global__ void finalK(const float* __restrict__ ft, float* __restrict__ out, int N) {
    if (threadIdx.x == 0) {
        float lf = 0.f;
        for (int k = 0; k < KC; k++) {
            float df = g_fill[k] / (float)N - ft[k];
            lf += df * df;
        }
        out[0] = g_loss + lf / (float)KC;
    }
}

template <int BT, int IPT>
static size_t wassSmem() {
    size_t a = sizeof(typename cub::BlockRadixSort<unsigned, BT, IPT>::TempStorage);
    size_t b = sizeof(PostTS<BT>);
    return a > b ? a : b;
}

extern "C" void kernel_launch(void* const* d_in, const int* in_sizes, int n_in,
                              void* d_out, int out_size) {
    const float* x  = (const float*)d_in[0];
    const float* C  = (const float*)d_in[1];
    const float* ft = (const float*)d_in[2];
    const float* tg = (const float*)d_in[3];
    const int*   pr = (const int*)d_in[4];
    float* out = (float*)d_out;
    int N = in_sizes[0] / DC;
    int nblk = (N + CHUNK - 1) / CHUNK;

    size_t s1 = wassSmem<256, 16>();
    size_t s2 = wassSmem<256, 32>();
    size_t s3 = wassSmem<512, 32>();
    size_t s4 = wassSmem<768, 32>();
    size_t s5 = wassSmem<512, 64>();
    cudaFuncSetAttribute(wassK<256, 16, 0>,      cudaFuncAttributeMaxDynamicSharedMemorySize, (int)s1);
    cudaFuncSetAttribute(wassK<256, 32, 4096>,   cudaFuncAttributeMaxDynamicSharedMemorySize, (int)s2);
    cudaFuncSetAttribute(wassK<512, 32, 8192>,   cudaFuncAttributeMaxDynamicSharedMemorySize, (int)s3);
    cudaFuncSetAttribute(wassK<768, 32, 16384>,  cudaFuncAttributeMaxDynamicSharedMemorySize, (int)s4);
    cudaFuncSetAttribute(wassK<512, 64, 24576>,  cudaFuncAttributeMaxDynamicSharedMemorySize, (int)s5);

    initK<<<1, 32>>>();
    assignK<<<nblk, 256>>>(x, C, N);
    countTK<<<nblk, 256>>>(pr, N);
    scanK<<<1, 1024>>>(nblk);
    fillK<<<2048, 256>>>();
    scatterK<<<nblk, 256>>>(x, pr, 1, N);
    scatterK<<<nblk, 256>>>(tg, pr, 0, N);
    wassK<256, 16, 0>      <<<KC * DC, 256, s1>>>();
    wassK<256, 32, 4096>   <<<KC * DC, 256, s2>>>();
    wassK<512, 32, 8192>   <<<KC * DC, 512, s3>>>();
    wassK<768, 32, 16384>  <<<KC * DC, 768, s4>>>();
    wassK<512, 64, 24576>  <<<KC * DC, 512, s5>>>();
    fallbackK<<<dim3(KC * DC, 2), 1024>>>();
    diffK<<<KC * DC, 256>>>();
    finalK<<<1, 32>>>(ft, out, N);
}

// round 4
// speedup vs baseline: 1.9911x; 1.9911x over previous
#include <cuda_runtime.h>
#include <cuda_bf16.h>
#include <cfloat>
#include <cub/cub.cuh>

#define KC 16
#define DC 64
#define NMAX 131072
#define CHUNK 256
#define NCHUNK_MAX (NMAX / CHUNK)

// ---------------- static device scratch ----------------
__device__ int   g_pred[NMAX];
__device__ int   g_ccx[NCHUNK_MAX * KC];
__device__ int   g_cct[NCHUNK_MAX * KC];
__device__ int   g_cbx[NCHUNK_MAX * KC];
__device__ int   g_cbt[NCHUNK_MAX * KC];
__device__ int   g_cntx[KC], g_cntt[KC], g_m[KC], g_off[KC], g_pow[KC];
__device__ float g_fill[KC];
__device__ float g_loss;
__device__ float g_bufx[2u * NMAX * DC];
__device__ float g_buft[2u * NMAX * DC];

// sortable-uint encode with LSB reserved for source tag (<=1ulp perturbation)
__device__ __forceinline__ unsigned encKey(float f) {
    unsigned u = __float_as_uint(f);
    unsigned s = (u & 0x80000000u) ? ~u : (u | 0x80000000u);
    return s & ~1u;
}
__device__ __forceinline__ float decKey(unsigned key) {
    unsigned s = key & ~1u;
    unsigned u = (s & 0x80000000u) ? (s & 0x7fffffffu) : ~s;
    return __uint_as_float(u);
}

// ---------------- init ----------------
__global__ void initK() {
    int t = threadIdx.x;
    if (t < KC) g_fill[t] = 0.f;
    if (t == 0) g_loss = 0.f;
}

// ---------------- assignment + softmax filling + per-chunk counts ----------------
__global__ void assignK(const float* __restrict__ x, const float* __restrict__ C, int N) {
    __shared__ float4 sC[KC * DC / 4];
    __shared__ float  sCC[KC];
    __shared__ float  sFill[KC];
    __shared__ int    sCnt[KC];
    int tid = threadIdx.x;
    sC[tid] = ((const float4*)C)[tid];
    if (tid < KC) { sFill[tid] = 0.f; sCnt[tid] = 0; }
    __syncthreads();
    if (tid < KC) {
        float cc = 0.f;
        #pragma unroll
        for (int q = 0; q < DC / 4; q++) {
            float4 c = sC[tid * (DC / 4) + q];
            cc += c.x * c.x + c.y * c.y + c.z * c.z + c.w * c.w;
        }
        sCC[tid] = cc;
    }
    __syncthreads();

    int i = blockIdx.x * blockDim.x + tid;
    bool act = i < N;
    float sc[KC];
    int bk = 0;
    if (act) {
        float acc[KC];
        #pragma unroll
        for (int k = 0; k < KC; k++) acc[k] = 0.f;
        const float4* xr = (const float4*)(x + (size_t)i * DC);
        #pragma unroll
        for (int q = 0; q < DC / 4; q++) {
            float4 v = xr[q];
            #pragma unroll
            for (int k = 0; k < KC; k++) {
                float4 c = sC[k * (DC / 4) + q];
                acc[k] += v.x * c.x + v.y * c.y + v.z * c.z + v.w * c.w;
            }
        }
        float best = FLT_MAX;
        #pragma unroll
        for (int k = 0; k < KC; k++) {
            sc[k] = sCC[k] - 2.f * acc[k];
            if (sc[k] < best) { best = sc[k]; bk = k; }
        }
        g_pred[i] = bk;
        float sum = 0.f;
        #pragma unroll
        for (int k = 0; k < KC; k++) { float e = __expf(-4.f * (sc[k] - best)); sc[k] = e; sum += e; }
        float inv = 1.f / sum;
        #pragma unroll
        for (int k = 0; k < KC; k++) sc[k] *= inv;
        atomicAdd(&sCnt[bk], 1);
    } else {
        #pragma unroll
        for (int k = 0; k < KC; k++) sc[k] = 0.f;
    }
    int lane = tid & 31;
    #pragma unroll
    for (int k = 0; k < KC; k++) {
        float v = sc[k];
        v += __shfl_down_sync(0xffffffffu, v, 16);
        v += __shfl_down_sync(0xffffffffu, v, 8);
        v += __shfl_down_sync(0xffffffffu, v, 4);
        v += __shfl_down_sync(0xffffffffu, v, 2);
        v += __shfl_down_sync(0xffffffffu, v, 1);
        if (lane == 0) atomicAdd(&sFill[k], v);
    }
    __syncthreads();
    if (tid < KC) {
        g_ccx[blockIdx.x * KC + tid] = sCnt[tid];
        atomicAdd(&g_fill[tid], sFill[tid]);
    }
}

// ---------------- per-chunk counts for target ----------------
__global__ void countTK(const int* __restrict__ pr, int N) {
    __shared__ int sCnt[KC];
    int tid = threadIdx.x;
    if (tid < KC) sCnt[tid] = 0;
    __syncthreads();
    int i = blockIdx.x * blockDim.x + tid;
    if (i < N) atomicAdd(&sCnt[pr[i]], 1);
    __syncthreads();
    if (tid < KC) g_cct[blockIdx.x * KC + tid] = sCnt[tid];
}

// ---------------- parallel scan: warp per (src,k) ----------------
__global__ void scanK(int nchunk) {
    int w = threadIdx.x >> 5, lane = threadIdx.x & 31;
    int k = w & 15;
    const int* cc = (w < 16) ? g_ccx : g_cct;
    int* cb       = (w < 16) ? g_cbx : g_cbt;
    int run = 0;
    for (int c0 = 0; c0 < nchunk; c0 += 32) {
        int c = c0 + lane;
        int v = (c < nchunk) ? cc[c * KC + k] : 0;
        int s = v;
        #pragma unroll
        for (int o = 1; o < 32; o <<= 1) {
            int y = __shfl_up_sync(0xffffffffu, s, o);
            if (lane >= o) s += y;
        }
        if (c < nchunk) cb[c * KC + k] = run + s - v;
        run += __shfl_sync(0xffffffffu, s, 31);
    }
    if (lane == 31) { if (w < 16) g_cntx[k] = run; else g_cntt[k] = run; }
    __syncthreads();
    if (threadIdx.x == 0) {
        int off = 0;
        for (int kk = 0; kk < KC; kk++) {
            int m = min(g_cntx[kk], g_cntt[kk]);
            g_m[kk] = m;
            int p = 1;
            while (p < m) p <<= 1;
            if (m == 0) p = 0;
            g_pow[kk] = p;
            g_off[kk] = off;
            off += p;
        }
    }
}

// ---------------- pad fill (only for giant-segment bitonic fallback) ----------------
__global__ void fillK() {
    int mx = 0;
    #pragma unroll
    for (int k = 0; k < KC; k++) mx = max(mx, g_m[k]);
    if (mx <= 49152) return;
    size_t n = (size_t)2 * NMAX * DC / 4;
    float4 v = make_float4(FLT_MAX, FLT_MAX, FLT_MAX, FLT_MAX);
    for (size_t i = (size_t)blockIdx.x * blockDim.x + threadIdx.x; i < n;
         i += (size_t)gridDim.x * blockDim.x) {
        ((float4*)g_bufx)[i] = v;
        ((float4*)g_buft)[i] = v;
    }
}

// ---------------- stable scatter into per-(cluster,dim) segments ----------------
__global__ void scatterK(const float* __restrict__ src, const int* __restrict__ predIn,
                         int isx, int N) {
    __shared__ int wcnt[8][KC];
    int tid = threadIdx.x;
    if (tid < 8 * KC) ((int*)wcnt)[tid] = 0;
    __syncthreads();
    const int* pred = isx ? g_pred : predIn;
    int i = blockIdx.x * blockDim.x + tid;
    int lane = tid & 31, w = tid >> 5;
    int k = 0, lr = 0;
    bool act = i < N;
    unsigned ball = __ballot_sync(0xffffffffu, act);
    if (act) {
        k = pred[i];
        unsigned mm = __match_any_sync(ball, k);
        lr = __popc(mm & ((1u << lane) - 1u));
        if (lane == (int)(__ffs(mm) - 1)) wcnt[w][k] = __popc(mm);
    }
    __syncthreads();
    if (act) {
        int base = isx ? g_cbx[blockIdx.x * KC + k] : g_cbt[blockIdx.x * KC + k];
        #pragma unroll
        for (int ww = 0; ww < 8; ww++)
            if (ww < w) base += wcnt[ww][k];
        int r = base + lr;
        int m = g_m[k];
        if (r < m) {
            int P = g_pow[k];
            float* buf = (isx ? g_bufx : g_buft) + (size_t)g_off[k] * DC + r;
            const float4* s4 = (const float4*)(src + (size_t)i * DC);
            #pragma unroll
            for (int q = 0; q < DC / 4; q++) {
                float4 v = s4[q];
                buf[(size_t)(4 * q + 0) * P] = v.x;
                buf[(size_t)(4 * q + 1) * P] = v.y;
                buf[(size_t)(4 * q + 2) * P] = v.z;
                buf[(size_t)(4 * q + 3) * P] = v.w;
            }
        }
    }
}

// ---------------- fused merged sort + W1 integral (2m <= 32768) ----------------
template <int BT>
struct PostTS {
    typename cub::BlockScan<int, BT>::TempStorage scan;
    typename cub::BlockReduce<float, BT>::TempStorage red;
    unsigned bound[BT];
};

template <int BT, int IPT, int LO>
__global__ void __launch_bounds__(BT) wassK() {
    constexpr int CAP = BT * IPT;
    int seg = blockIdx.x;
    int k = seg >> 6, d = seg & 63;
    int m = g_m[k];
    int twoM = 2 * m;
    if (m <= 0 || twoM <= LO || twoM > CAP) return;
    int P = g_pow[k];
    const float* bx = g_bufx + (size_t)g_off[k] * DC + (size_t)d * P;
    const float* bt = g_buft + (size_t)g_off[k] * DC + (size_t)d * P;

    typedef cub::BlockRadixSort<unsigned, BT, IPT> BRS;
    typedef cub::BlockScan<int, BT> BSc;
    typedef cub::BlockReduce<float, BT> BRd;
    extern __shared__ __align__(16) unsigned char smraw[];
    typename BRS::TempStorage* sortTS = reinterpret_cast<typename BRS::TempStorage*>(smraw);
    PostTS<BT>* post = reinterpret_cast<PostTS<BT>*>(smraw);

    unsigned keys[IPT];
    int base = threadIdx.x * IPT;
    #pragma unroll
    for (int j = 0; j < IPT; j++) {
        int idx = base + j;
        if (idx < m)            keys[j] = encKey(bx[idx]) | 1u;       // x: +1
        else if (idx < twoM)    keys[j] = encKey(bt[idx - m]);        // t: -1
        else                    keys[j] = 0xFFFFFFFFu;                // pad
    }
    BRS(*sortTS).Sort(keys);
    __syncthreads();

    int loc = 0;
    #pragma unroll
    for (int j = 0; j < IPT; j++) {
        int idx = base + j;
        if (idx < twoM) loc += (keys[j] & 1u) ? 1 : -1;
    }
    int off;
    BSc(post->scan).ExclusiveSum(loc, off);
    __syncthreads();
    post->bound[threadIdx.x] = keys[0];
    __syncthreads();
    unsigned nbound = (threadIdx.x + 1 < BT) ? post->bound[threadIdx.x + 1] : 0xFFFFFFFFu;

    float acc = 0.f;
    int run = off;
    #pragma unroll
    for (int j = 0; j < IPT; j++) {
        int idx = base + j;
        if (idx < twoM) run += (keys[j] & 1u) ? 1 : -1;
        if (idx + 1 < twoM) {
            unsigned nk = (j < IPT - 1) ? keys[j + 1] : nbound;
            acc += (decKey(nk) - decKey(keys[j])) * fabsf((float)run);
        }
    }
    __syncthreads();
    float tot = BRd(post->red).Sum(acc);
    if (threadIdx.x == 0) atomicAdd(&g_loss, tot / ((float)m * (float)DC));
}

// ---------------- split-path per-segment radix sorts (16384 < m <= 49152) ----------------
template <int BT, int IPT, int LO>
__global__ void __launch_bounds__(BT) sortTier() {
    constexpr int CAP = BT * IPT;
    int seg = blockIdx.x;
    int k = seg >> 6, d = seg & 63;
    int m = g_m[k];
    if (m <= LO || m > CAP) return;
    float* buf = (blockIdx.y ? g_buft : g_bufx) + (size_t)g_off[k] * DC + (size_t)d * g_pow[k];
    typedef cub::BlockRadixSort<float, BT, IPT> BRS;
    extern __shared__ __align__(16) unsigned char smraw[];
    typename BRS::TempStorage& ts = *reinterpret_cast<typename BRS::TempStorage*>(smraw);
    float items[IPT];
    int base = threadIdx.x * IPT;
    #pragma unroll
    for (int j = 0; j < IPT; j++) {
        int idx = base + j;
        items[j] = (idx < m) ? buf[idx] : FLT_MAX;
    }
    BRS(ts).Sort(items);
    #pragma unroll
    for (int j = 0; j < IPT; j++) {
        int idx = base + j;
        if (idx < m) buf[idx] = items[j];
    }
}

// ---------------- fallback: global bitonic for huge segments (m > 49152) ----------------
__global__ void fallbackK() {
    int seg = blockIdx.x;
    int k = seg >> 6, d = seg & 63;
    int m = g_m[k];
    if (m <= 49152) return;
    int P = g_pow[k];
    float* p = (blockIdx.y ? g_buft : g_bufx) + (size_t)g_off[k] * DC + (size_t)d * P;
    for (int size = 2; size <= P; size <<= 1) {
        for (int stride = size >> 1; stride; stride >>= 1) {
            for (int t = threadIdx.x; t < (P >> 1); t += blockDim.x) {
                int low = t & (stride - 1);
                int i = ((t - low) << 1) + low;
                int j = i + stride;
                float a = p[i], b = p[j];
                bool up = ((i & size) == 0);
                if ((a > b) == up) { p[i] = b; p[j] = a; }
            }
            __syncthreads();
        }
    }
}

// ---------------- diff for split/fallback path (m > 16384) ----------------
__global__ void diffK() {
    int seg = blockIdx.x;
    int k = seg >> 6, d = seg & 63;
    int m = g_m[k];
    if (m <= 16384) return;
    int P = g_pow[k];
    size_t base = (size_t)g_off[k] * DC + (size_t)d * P;
    float s = 0.f;
    for (int i = threadIdx.x; i < m; i += blockDim.x)
        s += fabsf(g_bufx[base + i] - g_buft[base + i]);
    __shared__ float red[256];
    red[threadIdx.x] = s;
    __syncthreads();
    for (int o = 128; o; o >>= 1) {
        if (threadIdx.x < o) red[threadIdx.x] += red[threadIdx.x + o];
        __syncthreads();
    }
    if (threadIdx.x == 0) atomicAdd(&g_loss, red[0] / ((float)m * (float)DC));
}

// ---------------- finalize ----------------
__global__ void finalK(const float* __restrict__ ft, float* __restrict__ out, int N) {
    if (threadIdx.x == 0) {
        float lf = 0.f;
        for (int k = 0; k < KC; k++) {
            float df = g_fill[k] / (float)N - ft[k];
            lf += df * df;
        }
        out[0] = g_loss + lf / (float)KC;
    }
}

template <int BT, int IPT>
static size_t wassSmem() {
    size_t a = sizeof(typename cub::BlockRadixSort<unsigned, BT, IPT>::TempStorage);
    size_t b = sizeof(PostTS<BT>);
    return a > b ? a : b;
}

extern "C" void kernel_launch(void* const* d_in, const int* in_sizes, int n_in,
                              void* d_out, int out_size) {
    const float* x  = (const float*)d_in[0];
    const float* C  = (const float*)d_in[1];
    const float* ft = (const float*)d_in[2];
    const float* tg = (const float*)d_in[3];
    const int*   pr = (const int*)d_in[4];
    float* out = (float*)d_out;
    int N = in_sizes[0] / DC;
    int nblk = (N + CHUNK - 1) / CHUNK;

    size_t w1 = wassSmem<512, 16>();
    size_t w2 = wassSmem<512, 32>();
    size_t w3 = wassSmem<1024, 32>();
    size_t t1 = sizeof(cub::BlockRadixSort<float, 1024, 32>::TempStorage);
    size_t t2 = sizeof(cub::BlockRadixSort<float, 512, 96>::TempStorage);
    cudaFuncSetAttribute(wassK<512, 16, 0>,        cudaFuncAttributeMaxDynamicSharedMemorySize, (int)w1);
    cudaFuncSetAttribute(wassK<512, 32, 8192>,     cudaFuncAttributeMaxDynamicSharedMemorySize, (int)w2);
    cudaFuncSetAttribute(wassK<1024, 32, 16384>,   cudaFuncAttributeMaxDynamicSharedMemorySize, (int)w3);
    cudaFuncSetAttribute(sortTier<1024, 32, 16384>, cudaFuncAttributeMaxDynamicSharedMemorySize, (int)t1);
    cudaFuncSetAttribute(sortTier<512, 96, 32768>,  cudaFuncAttributeMaxDynamicSharedMemorySize, (int)t2);

    initK<<<1, 32>>>();
    assignK<<<nblk, 256>>>(x, C, N);
    countTK<<<nblk, 256>>>(pr, N);
    scanK<<<1, 1024>>>(nblk);
    fillK<<<2048, 256>>>();
    scatterK<<<nblk, 256>>>(x, pr, 1, N);
    scatterK<<<nblk, 256>>>(tg, pr, 0, N);
    wassK<512, 16, 0>      <<<KC * DC, 512,  w1>>>();
    wassK<512, 32, 8192>   <<<KC * DC, 512,  w2>>>();
    wassK<1024, 32, 16384> <<<KC * DC, 1024, w3>>>();
    sortTier<1024, 32, 16384> <<<dim3(KC * DC, 2), 1024, t1>>>();
    sortTier<512, 96, 32768>  <<<dim3(KC * DC, 2), 512,  t2>>>();
    fallbackK<<<dim3(KC * DC, 2), 1024>>>();
    diffK<<<KC * DC, 256>>>();
    finalK<<<1, 32>>>(ft, out, N);
}

// round 6
// speedup vs baseline: 2.8121x; 1.4123x over previous
#include <cuda_runtime.h>
#include <cuda_bf16.h>
#include <cfloat>
#include <cub/cub.cuh>

#define KC 16
#define DC 64
#define NMAX 131072
#define CHUNK 256
#define NCHUNK_MAX (NMAX / CHUNK)

// ---------------- static device scratch ----------------
__device__ int   g_pred[NMAX];
__device__ int   g_ccx[NCHUNK_MAX * KC];
__device__ int   g_cct[NCHUNK_MAX * KC];
__device__ int   g_cbx[NCHUNK_MAX * KC];
__device__ int   g_cbt[NCHUNK_MAX * KC];
__device__ int   g_cntx[KC], g_cntt[KC], g_m[KC], g_off[KC], g_pow[KC];
__device__ float g_fill[KC];
__device__ float g_loss;
__device__ float g_bufx[2u * NMAX * DC];
__device__ float g_buft[2u * NMAX * DC];

// sortable-uint encode with LSB reserved for source tag (<=1ulp perturbation)
__device__ __forceinline__ unsigned encKey(float f) {
    unsigned u = __float_as_uint(f);
    unsigned s = (u & 0x80000000u) ? ~u : (u | 0x80000000u);
    return s & ~1u;
}
__device__ __forceinline__ float decKey(unsigned key) {
    unsigned s = key & ~1u;
    unsigned u = (s & 0x80000000u) ? (s & 0x7fffffffu) : ~s;
    return __uint_as_float(u);
}

// ---------------- init ----------------
__global__ void initK() {
    int t = threadIdx.x;
    if (t < KC) g_fill[t] = 0.f;
    if (t == 0) g_loss = 0.f;
}

// ---------------- assignment + softmax filling + per-chunk counts ----------------
__global__ void assignK(const float* __restrict__ x, const float* __restrict__ C, int N) {
    __shared__ float4 sC[KC * DC / 4];
    __shared__ float  sCC[KC];
    __shared__ float  sFill[KC];
    __shared__ int    sCnt[KC];
    int tid = threadIdx.x;
    sC[tid] = ((const float4*)C)[tid];
    if (tid < KC) { sFill[tid] = 0.f; sCnt[tid] = 0; }
    __syncthreads();
    if (tid < KC) {
        float cc = 0.f;
        #pragma unroll
        for (int q = 0; q < DC / 4; q++) {
            float4 c = sC[tid * (DC / 4) + q];
            cc += c.x * c.x + c.y * c.y + c.z * c.z + c.w * c.w;
        }
        sCC[tid] = cc;
    }
    __syncthreads();

    int i = blockIdx.x * blockDim.x + tid;
    bool act = i < N;
    float sc[KC];
    int bk = 0;
    if (act) {
        float acc[KC];
        #pragma unroll
        for (int k = 0; k < KC; k++) acc[k] = 0.f;
        const float4* xr = (const float4*)(x + (size_t)i * DC);
        #pragma unroll
        for (int q = 0; q < DC / 4; q++) {
            float4 v = xr[q];
            #pragma unroll
            for (int k = 0; k < KC; k++) {
                float4 c = sC[k * (DC / 4) + q];
                acc[k] += v.x * c.x + v.y * c.y + v.z * c.z + v.w * c.w;
            }
        }
        float best = FLT_MAX;
        #pragma unroll
        for (int k = 0; k < KC; k++) {
            sc[k] = sCC[k] - 2.f * acc[k];
            if (sc[k] < best) { best = sc[k]; bk = k; }
        }
        g_pred[i] = bk;
        float sum = 0.f;
        #pragma unroll
        for (int k = 0; k < KC; k++) { float e = __expf(-4.f * (sc[k] - best)); sc[k] = e; sum += e; }
        float inv = 1.f / sum;
        #pragma unroll
        for (int k = 0; k < KC; k++) sc[k] *= inv;
        atomicAdd(&sCnt[bk], 1);
    } else {
        #pragma unroll
        for (int k = 0; k < KC; k++) sc[k] = 0.f;
    }
    int lane = tid & 31;
    #pragma unroll
    for (int k = 0; k < KC; k++) {
        float v = sc[k];
        v += __shfl_down_sync(0xffffffffu, v, 16);
        v += __shfl_down_sync(0xffffffffu, v, 8);
        v += __shfl_down_sync(0xffffffffu, v, 4);
        v += __shfl_down_sync(0xffffffffu, v, 2);
        v += __shfl_down_sync(0xffffffffu, v, 1);
        if (lane == 0) atomicAdd(&sFill[k], v);
    }
    __syncthreads();
    if (tid < KC) {
        g_ccx[blockIdx.x * KC + tid] = sCnt[tid];
        atomicAdd(&g_fill[tid], sFill[tid]);
    }
}

// ---------------- per-chunk counts for target ----------------
__global__ void countTK(const int* __restrict__ pr, int N) {
    __shared__ int sCnt[KC];
    int tid = threadIdx.x;
    if (tid < KC) sCnt[tid] = 0;
    __syncthreads();
    int i = blockIdx.x * blockDim.x + tid;
    if (i < N) atomicAdd(&sCnt[pr[i]], 1);
    __syncthreads();
    if (tid < KC) g_cct[blockIdx.x * KC + tid] = sCnt[tid];
}

// ---------------- parallel scan: warp per (src,k) ----------------
__global__ void scanK(int nchunk) {
    int w = threadIdx.x >> 5, lane = threadIdx.x & 31;
    int k = w & 15;
    const int* cc = (w < 16) ? g_ccx : g_cct;
    int* cb       = (w < 16) ? g_cbx : g_cbt;
    int run = 0;
    for (int c0 = 0; c0 < nchunk; c0 += 32) {
        int c = c0 + lane;
        int v = (c < nchunk) ? cc[c * KC + k] : 0;
        int s = v;
        #pragma unroll
        for (int o = 1; o < 32; o <<= 1) {
            int y = __shfl_up_sync(0xffffffffu, s, o);
            if (lane >= o) s += y;
        }
        if (c < nchunk) cb[c * KC + k] = run + s - v;
        run += __shfl_sync(0xffffffffu, s, 31);
    }
    if (lane == 31) { if (w < 16) g_cntx[k] = run; else g_cntt[k] = run; }
    __syncthreads();
    if (threadIdx.x == 0) {
        int off = 0;
        for (int kk = 0; kk < KC; kk++) {
            int m = min(g_cntx[kk], g_cntt[kk]);
            g_m[kk] = m;
            int p = 1;
            while (p < m) p <<= 1;
            if (m == 0) p = 0;
            g_pow[kk] = p;
            g_off[kk] = off;
            off += p;
        }
    }
}

// ---------------- pad fill (only for giant-segment bitonic fallback) ----------------
__global__ void fillK() {
    int mx = 0;
    #pragma unroll
    for (int k = 0; k < KC; k++) mx = max(mx, g_m[k]);
    if (mx <= 49152) return;
    size_t n = (size_t)2 * NMAX * DC / 4;
    float4 v = make_float4(FLT_MAX, FLT_MAX, FLT_MAX, FLT_MAX);
    for (size_t i = (size_t)blockIdx.x * blockDim.x + threadIdx.x; i < n;
         i += (size_t)gridDim.x * blockDim.x) {
        ((float4*)g_bufx)[i] = v;
        ((float4*)g_buft)[i] = v;
    }
}

// ---------------- stable scatter into per-(cluster,dim) segments ----------------
__global__ void scatterK(const float* __restrict__ src, const int* __restrict__ predIn,
                         int isx, int N) {
    __shared__ int wcnt[8][KC];
    int tid = threadIdx.x;
    if (tid < 8 * KC) ((int*)wcnt)[tid] = 0;
    __syncthreads();
    const int* pred = isx ? g_pred : predIn;
    int i = blockIdx.x * blockDim.x + tid;
    int lane = tid & 31, w = tid >> 5;
    int k = 0, lr = 0;
    bool act = i < N;
    unsigned ball = __ballot_sync(0xffffffffu, act);
    if (act) {
        k = pred[i];
        unsigned mm = __match_any_sync(ball, k);
        lr = __popc(mm & ((1u << lane) - 1u));
        if (lane == (int)(__ffs(mm) - 1)) wcnt[w][k] = __popc(mm);
    }
    __syncthreads();
    if (act) {
        int base = isx ? g_cbx[blockIdx.x * KC + k] : g_cbt[blockIdx.x * KC + k];
        #pragma unroll
        for (int ww = 0; ww < 8; ww++)
            if (ww < w) base += wcnt[ww][k];
        int r = base + lr;
        int m = g_m[k];
        if (r < m) {
            int P = g_pow[k];
            float* buf = (isx ? g_bufx : g_buft) + (size_t)g_off[k] * DC + r;
            const float4* s4 = (const float4*)(src + (size_t)i * DC);
            #pragma unroll
            for (int q = 0; q < DC / 4; q++) {
                float4 v = s4[q];
                buf[(size_t)(4 * q + 0) * P] = v.x;
                buf[(size_t)(4 * q + 1) * P] = v.y;
                buf[(size_t)(4 * q + 2) * P] = v.z;
                buf[(size_t)(4 * q + 3) * P] = v.w;
            }
        }
    }
}

// ---------------- bucket-rank W1: no sort, per-item telescoped contribution ----------------
// loss_seg = sum_r v_r * (|run_{r-1}| - |run_r|), run_r = signed (#x - #t) prefix
// through global rank r. run computed as bucket-signed-prefix + within-bucket
// <=-count (slot-index tie-break -> strict total order).
template <int BT, int CAP, int B, int LO>
__global__ void __launch_bounds__(BT) wassB() {
    int seg = blockIdx.x;
    int k = seg >> 6, d = seg & 63;
    int m = g_m[k];
    int twoM = 2 * m;
    if (m <= 0 || twoM <= LO || twoM > CAP) return;
    int P = g_pow[k];
    const float* bx = g_bufx + (size_t)g_off[k] * DC + (size_t)d * P;
    const float* bt = g_buft + (size_t)g_off[k] * DC + (size_t)d * P;

    extern __shared__ __align__(16) unsigned char smraw[];
    unsigned* keys = (unsigned*)smraw;
    int* boff = (int*)(smraw + (size_t)CAP * 4);
    int* work = boff + B;
    int* sgn  = work + B;
    __shared__ int   warptmp[64];
    __shared__ float redtmp[32];

    int tid = threadIdx.x;
    int lane = tid & 31, wid = tid >> 5;
    constexpr int NW = BT / 32;
    constexpr int PER = B / BT;
    const float scale = (float)B / 12.f;

    for (int b = tid; b < B; b += BT) { work[b] = 0; sgn[b] = 0; }
    __syncthreads();

    // phase 1: bucket histogram (counts + signed)
    for (int i = tid; i < twoM; i += BT) {
        unsigned key = (i < m) ? (encKey(bx[i]) | 1u) : encKey(bt[i - m]);
        float v = decKey(key);                 // bucket from decoded value (consistent)
        int b = min(max((int)((v + 6.f) * scale), 0), B - 1);
        atomicAdd(&work[b], 1);
        atomicAdd(&sgn[b], (key & 1u) ? 1 : -1);
    }
    __syncthreads();

    // exclusive scans over B buckets: boff/work <- start offsets, sgn <- signed prefix
    {
        int c[PER], s[PER];
        #pragma unroll
        for (int j = 0; j < PER; j++) { c[j] = work[tid * PER + j]; s[j] = sgn[tid * PER + j]; }
        int csum = 0, ssum = 0;
        #pragma unroll
        for (int j = 0; j < PER; j++) {
            int t = c[j]; c[j] = csum; csum += t;
            t = s[j]; s[j] = ssum; ssum += t;
        }
        int ci = csum, si = ssum;
        #pragma unroll
        for (int o = 1; o < 32; o <<= 1) {
            int y = __shfl_up_sync(0xffffffffu, ci, o); if (lane >= o) ci += y;
            y     = __shfl_up_sync(0xffffffffu, si, o); if (lane >= o) si += y;
        }
        if (lane == 31) { warptmp[wid] = ci; warptmp[32 + wid] = si; }
        __syncthreads();
        if (wid == 0) {
            int a = (lane < NW) ? warptmp[lane] : 0;
            int bsg = (lane < NW) ? warptmp[32 + lane] : 0;
            #pragma unroll
            for (int o = 1; o < 32; o <<= 1) {
                int y = __shfl_up_sync(0xffffffffu, a, o);   if (lane >= o) a += y;
                y     = __shfl_up_sync(0xffffffffu, bsg, o); if (lane >= o) bsg += y;
            }
            warptmp[lane] = a; warptmp[32 + lane] = bsg;
        }
        __syncthreads();
        int cbase = ((wid ? warptmp[wid - 1] : 0)) + ci - csum;
        int sbase = ((wid ? warptmp[32 + wid - 1] : 0)) + si - ssum;
        __syncthreads();
        #pragma unroll
        for (int j = 0; j < PER; j++) {
            int idx = tid * PER + j;
            boff[idx] = cbase + c[j];
            work[idx] = cbase + c[j];
            sgn[idx]  = sbase + s[j];
        }
    }
    __syncthreads();

    // phase 2: scatter keys into bucket slots (order within bucket arbitrary)
    for (int i = tid; i < twoM; i += BT) {
        unsigned key = (i < m) ? (encKey(bx[i]) | 1u) : encKey(bt[i - m]);
        float v = decKey(key);
        int b = min(max((int)((v + 6.f) * scale), 0), B - 1);
        int pos = atomicAdd(&work[b], 1);
        keys[pos] = key;
    }
    __syncthreads();

    // phase 3: per-item contribution
    float acc = 0.f;
    for (int s_ = tid; s_ < twoM; s_ += BT) {
        unsigned kk = keys[s_];
        float v = decKey(kk);
        int b = min(max((int)((v + 6.f) * scale), 0), B - 1);
        int st = boff[b], en = work[b];
        int run = sgn[b];
        int mytag = (kk & 1u) ? 1 : -1;
        for (int j = st; j < en; j++) {
            unsigned kj = keys[j];
            bool le = (kj < kk) || (kj == kk && j <= s_);
            if (le) run += (kj & 1u) ? 1 : -1;
        }
        acc += v * (fabsf((float)(run - mytag)) - fabsf((float)run));
    }

    // block reduce
    #pragma unroll
    for (int o = 16; o; o >>= 1) acc += __shfl_down_sync(0xffffffffu, acc, o);
    if (lane == 0) redtmp[wid] = acc;
    __syncthreads();
    if (wid == 0) {
        float t = (lane < NW) ? redtmp[lane] : 0.f;
        #pragma unroll
        for (int o = 16; o; o >>= 1) t += __shfl_down_sync(0xffffffffu, t, o);
        if (lane == 0) atomicAdd(&g_loss, t / ((float)m * (float)DC));
    }
}

// ---------------- split-path radix sorts for m > 16384 ----------------
template <int BT, int IPT, int LO>
__global__ void __launch_bounds__(BT) sortTier() {
    constexpr int CAP = BT * IPT;
    int seg = blockIdx.x;
    int k = seg >> 6, d = seg & 63;
    int m = g_m[k];
    if (m <= LO || m > CAP) return;
    float* buf = (blockIdx.y ? g_buft : g_bufx) + (size_t)g_off[k] * DC + (size_t)d * g_pow[k];
    typedef cub::BlockRadixSort<float, BT, IPT> BRS;
    extern __shared__ __align__(16) unsigned char smraw[];
    typename BRS::TempStorage& ts = *reinterpret_cast<typename BRS::TempStorage*>(smraw);
    float items[IPT];
    int base = threadIdx.x * IPT;
    #pragma unroll
    for (int j = 0; j < IPT; j++) {
        int idx = base + j;
        items[j] = (idx < m) ? buf[idx] : FLT_MAX;
    }
    BRS(ts).Sort(items);
    #pragma unroll
    for (int j = 0; j < IPT; j++) {
        int idx = base + j;
        if (idx < m) buf[idx] = items[j];
    }
}

// ---------------- fallback: global bitonic for huge segments (m > 49152) ----------------
__global__ void fallbackK() {
    int seg = blockIdx.x;
    int k = seg >> 6, d = seg & 63;
    int m = g_m[k];
    if (m <= 49152) return;
    int P = g_pow[k];
    float* p = (blockIdx.y ? g_buft : g_bufx) + (size_t)g_off[k] * DC + (size_t)d * P;
    for (int size = 2; size <= P; size <<= 1) {
        for (int stride = size >> 1; stride; stride >>= 1) {
            for (int t = threadIdx.x; t < (P >> 1); t += blockDim.x) {
                int low = t & (stride - 1);
                int i = ((t - low) << 1) + low;
                int j = i + stride;
                float a = p[i], b = p[j];
                bool up = ((i & size) == 0);
                if ((a > b) == up) { p[i] = b; p[j] = a; }
            }
            __syncthreads();
        }
    }
}

// ---------------- diff for split/fallback path (m > 16384) ----------------
__global__ void diffK() {
    int seg = blockIdx.x;
    int k = seg >> 6, d = seg & 63;
    int m = g_m[k];
    if (m <= 16384) return;
    int P = g_pow[k];
    size_t base = (size_t)g_off[k] * DC + (size_t)d * P;
    float s = 0.f;
    for (int i = threadIdx.x; i < m; i += blockDim.x)
        s += fabsf(g_bufx[base + i] - g_buft[base + i]);
    __shared__ float red[256];
    red[threadIdx.x] = s;
    __syncthreads();
    for (int o = 128; o; o >>= 1) {
        if (threadIdx.x < o) red[threadIdx.x] += red[threadIdx.x + o];
        __syncthreads();
    }
    if (threadIdx.x == 0) atomicAdd(&g_loss, red[0] / ((float)m * (float)DC));
}

// ---------------- finalize ----------------
__global__ void finalK(const float* __restrict__ ft, float* __restrict__ out, int N) {
    if (threadIdx.x == 0) {
        float lf = 0.f;
        for (int k = 0; k < KC; k++) {
            float df = g_fill[k] / (float)N - ft[k];
            lf += df * df;
        }
        out[0] = g_loss + lf / (float)KC;
    }
}

extern "C" void kernel_launch(void* const* d_in, const int* in_sizes, int n_in,
                              void* d_out, int out_size) {
    const float* x  = (const float*)d_in[0];
    const float* C  = (const float*)d_in[1];
    const float* ft = (const float*)d_in[2];
    const float* tg = (const float*)d_in[3];
    const int*   pr = (const int*)d_in[4];
    float* out = (float*)d_out;
    int N = in_sizes[0] / DC;
    int nblk = (N + CHUNK - 1) / CHUNK;

    // bucket-rank tiers
    size_t b1 = (size_t)8192 * 4 + 3 * 2048 * 4;    //  56 KB
    size_t b2 = (size_t)16384 * 4 + 3 * 4096 * 4;   // 112 KB
    size_t b3 = (size_t)32768 * 4 + 3 * 8192 * 4;   // 224 KB
    cudaFuncSetAttribute(wassB<256, 8192, 2048, 0>,      cudaFuncAttributeMaxDynamicSharedMemorySize, (int)b1);
    cudaFuncSetAttribute(wassB<512, 16384, 4096, 8192>,  cudaFuncAttributeMaxDynamicSharedMemorySize, (int)b2);
    cudaFuncSetAttribute(wassB<512, 32768, 8192, 16384>, cudaFuncAttributeMaxDynamicSharedMemorySize, (int)b3);
    // split radix tiers for big clusters
    size_t t1 = sizeof(cub::BlockRadixSort<float, 512, 64>::TempStorage);
    size_t t2 = sizeof(cub::BlockRadixSort<float, 512, 96>::TempStorage);
    cudaFuncSetAttribute(sortTier<512, 64, 16384>, cudaFuncAttributeMaxDynamicSharedMemorySize, (int)t1);
    cudaFuncSetAttribute(sortTier<512, 96, 32768>, cudaFuncAttributeMaxDynamicSharedMemorySize, (int)t2);

    initK<<<1, 32>>>();
    assignK<<<nblk, 256>>>(x, C, N);
    countTK<<<nblk, 256>>>(pr, N);
    scanK<<<1, 1024>>>(nblk);
    fillK<<<2048, 256>>>();
    scatterK<<<nblk, 256>>>(x, pr, 1, N);
    scatterK<<<nblk, 256>>>(tg, pr, 0, N);
    wassB<256, 8192, 2048, 0>      <<<KC * DC, 256, b1>>>();
    wassB<512, 16384, 4096, 8192>  <<<KC * DC, 512, b2>>>();
    wassB<512, 32768, 8192, 16384> <<<KC * DC, 512, b3>>>();
    sortTier<512, 64, 16384> <<<dim3(KC * DC, 2), 512, t1>>>();
    sortTier<512, 96, 32768> <<<dim3(KC * DC, 2), 512, t2>>>();
    fallbackK<<<dim3(KC * DC, 2), 1024>>>();
    diffK<<<KC * DC, 256>>>();
    finalK<<<1, 32>>>(ft, out, N);
}

// round 7
// speedup vs baseline: 3.8150x; 1.3566x over previous
#include <cuda_runtime.h>
#include <cuda_bf16.h>
#include <cfloat>

#define KC 16
#define DC 64
#define NMAX 131072
#define CHUNK 256
#define NCHUNK_MAX (NMAX / CHUNK)

// ---------------- static device scratch ----------------
__device__ int   g_pred[NMAX];
__device__ int   g_ccx[NCHUNK_MAX * KC];
__device__ int   g_cct[NCHUNK_MAX * KC];
__device__ int   g_cbx[NCHUNK_MAX * KC];
__device__ int   g_cbt[NCHUNK_MAX * KC];
__device__ int   g_cntx[KC], g_cntt[KC], g_m[KC], g_off[KC], g_pow[KC];
__device__ float g_fill[KC];
__device__ float g_loss;
__device__ float g_bufx[2u * NMAX * DC];
__device__ float g_buft[2u * NMAX * DC];
__device__ unsigned g_scr[4u * NMAX * DC];   // XL-tier global key scratch

// sortable-uint encode with LSB reserved for source tag (<=1ulp perturbation)
__device__ __forceinline__ unsigned encKey(float f) {
    unsigned u = __float_as_uint(f);
    unsigned s = (u & 0x80000000u) ? ~u : (u | 0x80000000u);
    return s & ~1u;
}
__device__ __forceinline__ float decKey(unsigned key) {
    unsigned s = key & ~1u;
    unsigned u = (s & 0x80000000u) ? (s & 0x7fffffffu) : ~s;
    return __uint_as_float(u);
}

// ---------------- init ----------------
__global__ void initK() {
    int t = threadIdx.x;
    if (t < KC) g_fill[t] = 0.f;
    if (t == 0) g_loss = 0.f;
}

// ---------------- assignment + softmax filling + per-chunk counts ----------------
__global__ void assignK(const float* __restrict__ x, const float* __restrict__ C, int N) {
    __shared__ float4 sC[KC * DC / 4];
    __shared__ float  sCC[KC];
    __shared__ float  sFill[KC];
    __shared__ int    sCnt[KC];
    int tid = threadIdx.x;
    sC[tid] = ((const float4*)C)[tid];
    if (tid < KC) { sFill[tid] = 0.f; sCnt[tid] = 0; }
    __syncthreads();
    if (tid < KC) {
        float cc = 0.f;
        #pragma unroll
        for (int q = 0; q < DC / 4; q++) {
            float4 c = sC[tid * (DC / 4) + q];
            cc += c.x * c.x + c.y * c.y + c.z * c.z + c.w * c.w;
        }
        sCC[tid] = cc;
    }
    __syncthreads();

    int i = blockIdx.x * blockDim.x + tid;
    bool act = i < N;
    float sc[KC];
    int bk = 0;
    if (act) {
        float acc[KC];
        #pragma unroll
        for (int k = 0; k < KC; k++) acc[k] = 0.f;
        const float4* xr = (const float4*)(x + (size_t)i * DC);
        #pragma unroll
        for (int q = 0; q < DC / 4; q++) {
            float4 v = xr[q];
            #pragma unroll
            for (int k = 0; k < KC; k++) {
                float4 c = sC[k * (DC / 4) + q];
                acc[k] += v.x * c.x + v.y * c.y + v.z * c.z + v.w * c.w;
            }
        }
        float best = FLT_MAX;
        #pragma unroll
        for (int k = 0; k < KC; k++) {
            sc[k] = sCC[k] - 2.f * acc[k];
            if (sc[k] < best) { best = sc[k]; bk = k; }
        }
        g_pred[i] = bk;
        float sum = 0.f;
        #pragma unroll
        for (int k = 0; k < KC; k++) { float e = __expf(-4.f * (sc[k] - best)); sc[k] = e; sum += e; }
        float inv = 1.f / sum;
        #pragma unroll
        for (int k = 0; k < KC; k++) sc[k] *= inv;
        atomicAdd(&sCnt[bk], 1);
    } else {
        #pragma unroll
        for (int k = 0; k < KC; k++) sc[k] = 0.f;
    }
    int lane = tid & 31;
    #pragma unroll
    for (int k = 0; k < KC; k++) {
        float v = sc[k];
        v += __shfl_down_sync(0xffffffffu, v, 16);
        v += __shfl_down_sync(0xffffffffu, v, 8);
        v += __shfl_down_sync(0xffffffffu, v, 4);
        v += __shfl_down_sync(0xffffffffu, v, 2);
        v += __shfl_down_sync(0xffffffffu, v, 1);
        if (lane == 0) atomicAdd(&sFill[k], v);
    }
    __syncthreads();
    if (tid < KC) {
        g_ccx[blockIdx.x * KC + tid] = sCnt[tid];
        atomicAdd(&g_fill[tid], sFill[tid]);
    }
}

// ---------------- per-chunk counts for target ----------------
__global__ void countTK(const int* __restrict__ pr, int N) {
    __shared__ int sCnt[KC];
    int tid = threadIdx.x;
    if (tid < KC) sCnt[tid] = 0;
    __syncthreads();
    int i = blockIdx.x * blockDim.x + tid;
    if (i < N) atomicAdd(&sCnt[pr[i]], 1);
    __syncthreads();
    if (tid < KC) g_cct[blockIdx.x * KC + tid] = sCnt[tid];
}

// ---------------- parallel scan: warp per (src,k) ----------------
__global__ void scanK(int nchunk) {
    int w = threadIdx.x >> 5, lane = threadIdx.x & 31;
    int k = w & 15;
    const int* cc = (w < 16) ? g_ccx : g_cct;
    int* cb       = (w < 16) ? g_cbx : g_cbt;
    int run = 0;
    for (int c0 = 0; c0 < nchunk; c0 += 32) {
        int c = c0 + lane;
        int v = (c < nchunk) ? cc[c * KC + k] : 0;
        int s = v;
        #pragma unroll
        for (int o = 1; o < 32; o <<= 1) {
            int y = __shfl_up_sync(0xffffffffu, s, o);
            if (lane >= o) s += y;
        }
        if (c < nchunk) cb[c * KC + k] = run + s - v;
        run += __shfl_sync(0xffffffffu, s, 31);
    }
    if (lane == 31) { if (w < 16) g_cntx[k] = run; else g_cntt[k] = run; }
    __syncthreads();
    if (threadIdx.x == 0) {
        int off = 0;
        for (int kk = 0; kk < KC; kk++) {
            int m = min(g_cntx[kk], g_cntt[kk]);
            g_m[kk] = m;
            int p = 1;
            while (p < m) p <<= 1;
            if (m == 0) p = 0;
            g_pow[kk] = p;
            g_off[kk] = off;
            off += p;
        }
    }
}

// ---------------- stable scatter into per-(cluster,dim) segments ----------------
__global__ void scatterK(const float* __restrict__ src, const int* __restrict__ predIn,
                         int isx, int N) {
    __shared__ int wcnt[8][KC];
    int tid = threadIdx.x;
    if (tid < 8 * KC) ((int*)wcnt)[tid] = 0;
    __syncthreads();
    const int* pred = isx ? g_pred : predIn;
    int i = blockIdx.x * blockDim.x + tid;
    int lane = tid & 31, w = tid >> 5;
    int k = 0, lr = 0;
    bool act = i < N;
    unsigned ball = __ballot_sync(0xffffffffu, act);
    if (act) {
        k = pred[i];
        unsigned mm = __match_any_sync(ball, k);
        lr = __popc(mm & ((1u << lane) - 1u));
        if (lane == (int)(__ffs(mm) - 1)) wcnt[w][k] = __popc(mm);
    }
    __syncthreads();
    if (act) {
        int base = isx ? g_cbx[blockIdx.x * KC + k] : g_cbt[blockIdx.x * KC + k];
        #pragma unroll
        for (int ww = 0; ww < 8; ww++)
            if (ww < w) base += wcnt[ww][k];
        int r = base + lr;
        int m = g_m[k];
        if (r < m) {
            int P = g_pow[k];
            float* buf = (isx ? g_bufx : g_buft) + (size_t)g_off[k] * DC + r;
            const float4* s4 = (const float4*)(src + (size_t)i * DC);
            #pragma unroll
            for (int q = 0; q < DC / 4; q++) {
                float4 v = s4[q];
                buf[(size_t)(4 * q + 0) * P] = v.x;
                buf[(size_t)(4 * q + 1) * P] = v.y;
                buf[(size_t)(4 * q + 2) * P] = v.z;
                buf[(size_t)(4 * q + 3) * P] = v.w;
            }
        }
    }
}

// ==================== bucket-rank W1 with sign fast-path ====================
// Per-item contribution is exactly +-v; the sign depends only on the sign of the
// signed run at the item's rank. All within-bucket partial prefixes lie in
// [run0 - n_b, run0 + n_b], so |run0| > n_b decides the sign with no inner loop.

// block-wide double exclusive scan over B entries stored in boff (counts) & sgn
template <int BT, int B>
__device__ __forceinline__ void scan2(int* boff, int* sgn, int* warptmp) {
    constexpr int NW = BT / 32;
    constexpr int PER = B / BT;
    int tid = threadIdx.x, lane = tid & 31, wid = tid >> 5;
    int c[PER], s[PER];
    #pragma unroll
    for (int j = 0; j < PER; j++) { c[j] = boff[tid * PER + j]; s[j] = sgn[tid * PER + j]; }
    int csum = 0, ssum = 0;
    #pragma unroll
    for (int j = 0; j < PER; j++) {
        int t = c[j]; c[j] = csum; csum += t;
        t = s[j]; s[j] = ssum; ssum += t;
    }
    int ci = csum, si = ssum;
    #pragma unroll
    for (int o = 1; o < 32; o <<= 1) {
        int y = __shfl_up_sync(0xffffffffu, ci, o); if (lane >= o) ci += y;
        y     = __shfl_up_sync(0xffffffffu, si, o); if (lane >= o) si += y;
    }
    if (lane == 31) { warptmp[wid] = ci; warptmp[32 + wid] = si; }
    __syncthreads();
    if (wid == 0) {
        int a = (lane < NW) ? warptmp[lane] : 0;
        int b2 = (lane < NW) ? warptmp[32 + lane] : 0;
        #pragma unroll
        for (int o = 1; o < 32; o <<= 1) {
            int y = __shfl_up_sync(0xffffffffu, a, o);  if (lane >= o) a += y;
            y     = __shfl_up_sync(0xffffffffu, b2, o); if (lane >= o) b2 += y;
        }
        warptmp[lane] = a; warptmp[32 + lane] = b2;
    }
    __syncthreads();
    int cbase = ((wid ? warptmp[wid - 1] : 0)) + ci - csum;
    int sbase = ((wid ? warptmp[32 + wid - 1] : 0)) + si - ssum;
    __syncthreads();
    #pragma unroll
    for (int j = 0; j < PER; j++) {
        int idx = tid * PER + j;
        boff[idx] = cbase + c[j];   // exclusive count prefix = start offset (becomes cursor)
        sgn[idx]  = sbase + s[j];   // exclusive signed prefix
    }
}

template <int BT>
__device__ __forceinline__ void blockReduceAdd(float acc, int m, float* redtmp) {
    constexpr int NW = BT / 32;
    int lane = threadIdx.x & 31, wid = threadIdx.x >> 5;
    #pragma unroll
    for (int o = 16; o; o >>= 1) acc += __shfl_down_sync(0xffffffffu, acc, o);
    if (lane == 0) redtmp[wid] = acc;
    __syncthreads();
    if (wid == 0) {
        float t = (lane < NW) ? redtmp[lane] : 0.f;
        #pragma unroll
        for (int o = 16; o; o >>= 1) t += __shfl_down_sync(0xffffffffu, t, o);
        if (lane == 0) atomicAdd(&g_loss, t / ((float)m * (float)DC));
    }
}

template <int BT, int CAP, int B, int LO>
__global__ void __launch_bounds__(BT) wassB() {
    int seg = blockIdx.x;
    int k = seg >> 6, d = seg & 63;
    int m = g_m[k];
    int twoM = 2 * m;
    if (m <= 0 || twoM <= LO || twoM > CAP) return;
    int P = g_pow[k];
    const float* bx = g_bufx + (size_t)g_off[k] * DC + (size_t)d * P;
    const float* bt = g_buft + (size_t)g_off[k] * DC + (size_t)d * P;

    extern __shared__ __align__(16) unsigned char smraw[];
    unsigned* keys = (unsigned*)smraw;
    int* boff = (int*)(smraw + (size_t)CAP * 4);
    int* sgn  = boff + B;
    __shared__ int   warptmp[64];
    __shared__ float redtmp[32];

    int tid = threadIdx.x;
    const float scale = (float)B / 12.f;

    for (int b = tid; b < B; b += BT) { boff[b] = 0; sgn[b] = 0; }
    __syncthreads();

    // phase 1: histogram (counts into boff, signed into sgn)
    for (int i = tid; i < twoM; i += BT) {
        unsigned key = (i < m) ? (encKey(bx[i]) | 1u) : encKey(bt[i - m]);
        float v = decKey(key);
        int b = min(max((int)((v + 6.f) * scale), 0), B - 1);
        atomicAdd(&boff[b], 1);
        atomicAdd(&sgn[b], (key & 1u) ? 1 : -1);
    }
    __syncthreads();

    scan2<BT, B>(boff, sgn, warptmp);
    __syncthreads();

    // phase 2: scatter keys into bucket slots (boff doubles as cursor; ends at bucket end)
    for (int i = tid; i < twoM; i += BT) {
        unsigned key = (i < m) ? (encKey(bx[i]) | 1u) : encKey(bt[i - m]);
        float v = decKey(key);
        int b = min(max((int)((v + 6.f) * scale), 0), B - 1);
        int pos = atomicAdd(&boff[b], 1);
        keys[pos] = key;
    }
    __syncthreads();

    // phase 3: per-item +-v with sign fast-path
    float acc = 0.f;
    for (int s_ = tid; s_ < twoM; s_ += BT) {
        unsigned kk = keys[s_];
        float v = decKey(kk);
        int b = min(max((int)((v + 6.f) * scale), 0), B - 1);
        int st = b ? boff[b - 1] : 0;
        int en = boff[b];
        int nb = en - st;
        int run0 = sgn[b];
        int mytag = (kk & 1u) ? 1 : -1;
        if (run0 > nb)        acc -= (float)mytag * v;
        else if (run0 < -nb)  acc += (float)mytag * v;
        else {
            int run = run0;
            for (int j = st; j < en; j++) {
                unsigned kj = keys[j];
                bool le = (kj < kk) || (kj == kk && j <= s_);
                if (le) run += (kj & 1u) ? 1 : -1;
            }
            acc += v * (fabsf((float)(run - mytag)) - fabsf((float)run));
        }
    }
    __syncthreads();
    blockReduceAdd<BT>(acc, m, redtmp);
}

// XL tier: keys in global scratch, any size (2m > LO)
template <int BT, int B, int LO>
__global__ void __launch_bounds__(BT) wassXL() {
    int seg = blockIdx.x;
    int k = seg >> 6, d = seg & 63;
    int m = g_m[k];
    int twoM = 2 * m;
    if (m <= 0 || twoM <= LO) return;
    int P = g_pow[k];
    const float* bx = g_bufx + (size_t)g_off[k] * DC + (size_t)d * P;
    const float* bt = g_buft + (size_t)g_off[k] * DC + (size_t)d * P;
    unsigned* keys = g_scr + (size_t)g_off[k] * 2 * DC + (size_t)d * 2 * P;

    extern __shared__ __align__(16) unsigned char smraw[];
    int* boff = (int*)smraw;
    int* sgn  = boff + B;
    __shared__ int   warptmp[64];
    __shared__ float redtmp[32];

    int tid = threadIdx.x;
    const float scale = (float)B / 12.f;

    for (int b = tid; b < B; b += BT) { boff[b] = 0; sgn[b] = 0; }
    __syncthreads();

    for (int i = tid; i < twoM; i += BT) {
        unsigned key = (i < m) ? (encKey(bx[i]) | 1u) : encKey(bt[i - m]);
        float v = decKey(key);
        int b = min(max((int)((v + 6.f) * scale), 0), B - 1);
        atomicAdd(&boff[b], 1);
        atomicAdd(&sgn[b], (key & 1u) ? 1 : -1);
    }
    __syncthreads();

    scan2<BT, B>(boff, sgn, warptmp);
    __syncthreads();

    for (int i = tid; i < twoM; i += BT) {
        unsigned key = (i < m) ? (encKey(bx[i]) | 1u) : encKey(bt[i - m]);
        float v = decKey(key);
        int b = min(max((int)((v + 6.f) * scale), 0), B - 1);
        int pos = atomicAdd(&boff[b], 1);
        keys[pos] = key;
    }
    __syncthreads();

    float acc = 0.f;
    for (int s_ = tid; s_ < twoM; s_ += BT) {
        unsigned kk = keys[s_];
        float v = decKey(kk);
        int b = min(max((int)((v + 6.f) * scale), 0), B - 1);
        int st = b ? boff[b - 1] : 0;
        int en = boff[b];
        int nb = en - st;
        int run0 = sgn[b];
        int mytag = (kk & 1u) ? 1 : -1;
        if (run0 > nb)        acc -= (float)mytag * v;
        else if (run0 < -nb)  acc += (float)mytag * v;
        else {
            int run = run0;
            for (int j = st; j < en; j++) {
                unsigned kj = keys[j];
                bool le = (kj < kk) || (kj == kk && j <= s_);
                if (le) run += (kj & 1u) ? 1 : -1;
            }
            acc += v * (fabsf((float)(run - mytag)) - fabsf((float)run));
        }
    }
    __syncthreads();
    blockReduceAdd<BT>(acc, m, redtmp);
}

// ---------------- finalize ----------------
__global__ void finalK(const float* __restrict__ ft, float* __restrict__ out, int N) {
    if (threadIdx.x == 0) {
        float lf = 0.f;
        for (int k = 0; k < KC; k++) {
            float df = g_fill[k] / (float)N - ft[k];
            lf += df * df;
        }
        out[0] = g_loss + lf / (float)KC;
    }
}

extern "C" void kernel_launch(void* const* d_in, const int* in_sizes, int n_in,
                              void* d_out, int out_size) {
    const float* x  = (const float*)d_in[0];
    const float* C  = (const float*)d_in[1];
    const float* ft = (const float*)d_in[2];
    const float* tg = (const float*)d_in[3];
    const int*   pr = (const int*)d_in[4];
    float* out = (float*)d_out;
    int N = in_sizes[0] / DC;
    int nblk = (N + CHUNK - 1) / CHUNK;

    size_t b1 = (size_t)8192 * 4  + 2 * 4096 * 4;   //  64 KB
    size_t b2 = (size_t)16384 * 4 + 2 * 4096 * 4;   //  96 KB
    size_t b3 = (size_t)32768 * 4 + 2 * 8192 * 4;   // 192 KB
    size_t bx = 2 * 8192 * 4;                        //  64 KB
    cudaFuncSetAttribute(wassB<256, 8192, 4096, 0>,      cudaFuncAttributeMaxDynamicSharedMemorySize, (int)b1);
    cudaFuncSetAttribute(wassB<512, 16384, 4096, 8192>,  cudaFuncAttributeMaxDynamicSharedMemorySize, (int)b2);
    cudaFuncSetAttribute(wassB<512, 32768, 8192, 16384>, cudaFuncAttributeMaxDynamicSharedMemorySize, (int)b3);
    cudaFuncSetAttribute(wassXL<512, 8192, 32768>,       cudaFuncAttributeMaxDynamicSharedMemorySize, (int)bx);

    initK<<<1, 32>>>();
    assignK<<<nblk, 256>>>(x, C, N);
    countTK<<<nblk, 256>>>(pr, N);
    scanK<<<1, 1024>>>(nblk);
    scatterK<<<nblk, 256>>>(x, pr, 1, N);
    scatterK<<<nblk, 256>>>(tg, pr, 0, N);
    wassB<256, 8192, 4096, 0>      <<<KC * DC, 256, b1>>>();
    wassB<512, 16384, 4096, 8192>  <<<KC * DC, 512, b2>>>();
    wassB<512, 32768, 8192, 16384> <<<KC * DC, 512, b3>>>();
    wassXL<512, 8192, 32768>       <<<KC * DC, 512, bx>>>();
    finalK<<<1, 32>>>(ft, out, N);
}